// round 17
// baseline (speedup 1.0000x reference)
#include <cuda_runtime.h>
#include <cuda_bf16.h>
#include <cuda_fp16.h>
#include <cstdint>
#include <math.h>

// Problem constants
#define BATCH 32
#define CCH   128
#define NTOK  4096
#define NH    4
#define DH    32
#define QKV3  384
#define NSPLIT 4

// ---------------- scratch (device globals; no allocation allowed) ----------
__device__ __half g_qkvh[(size_t)BATCH * QKV3 * NTOK];        // q, exp(k), v (fp16)
__device__ __half g_wth[QKV3 * CCH];                          // g-folded W, fp16
__device__ float g_ctx_part[NSPLIT * BATCH * NH * DH * DH];
__device__ float g_zpart[NSPLIT * BATCH * NH * DH];
__device__ __half g_w2h[BATCH * CCH * CCH];                   // W2 fp16: [b][o][c]

__device__ __forceinline__ uint32_t smem_u32(const void* p) {
    uint32_t a;
    asm("{ .reg .u64 t; cvta.to.shared.u64 t, %1; cvt.u32.u64 %0, t; }"
        : "=r"(a) : "l"(p));
    return a;
}
__device__ __forceinline__ void mma_f16(float* d, uint32_t a0, uint32_t a1,
                                        uint32_t a2, uint32_t a3,
                                        uint32_t b0, uint32_t b1) {
    asm volatile(
        "mma.sync.aligned.m16n8k16.row.col.f32.f16.f16.f32 "
        "{%0,%1,%2,%3}, {%4,%5,%6,%7}, {%8,%9}, {%0,%1,%2,%3};"
        : "+f"(d[0]), "+f"(d[1]), "+f"(d[2]), "+f"(d[3])
        : "r"(a0), "r"(a1), "r"(a2), "r"(a3), "r"(b0), "r"(b1));
}
__device__ __forceinline__ void ldsm_x4(uint32_t& r0, uint32_t& r1, uint32_t& r2,
                                        uint32_t& r3, uint32_t addr) {
    asm volatile("ldmatrix.sync.aligned.m8n8.x4.shared.b16 {%0,%1,%2,%3}, [%4];"
                 : "=r"(r0), "=r"(r1), "=r"(r2), "=r"(r3) : "r"(addr));
}
__device__ __forceinline__ void ldsm_x2(uint32_t& r0, uint32_t& r1, uint32_t addr) {
    asm volatile("ldmatrix.sync.aligned.m8n8.x2.shared.b16 {%0,%1}, [%2];"
                 : "=r"(r0), "=r"(r1) : "r"(addr));
}

#define PITCH 136   // halfs; 272 B row stride -> conflict-free ldmatrix

// ============================================================================
// K0: fold g[k]*sqrt(C) into qkv weights, store fp16.
// ============================================================================
__global__ void k_prepw(const float* __restrict__ wqkv, const float* __restrict__ g) {
    int i = blockIdx.x * 256 + threadIdx.x;
    int k = i & 127;
    float w = wqkv[i] * g[k] * 11.313708498984761f;
    g_wth[i] = __float2half(w);
}

// ============================================================================
// K1: fused RMSNorm + qkv GEMM on fp16 HMMA + ldmatrix.
// Per CTA: 128 tokens (2 x 64 halves), all 3 mt tiles; x staged + normed once,
// W tile loaded once per mt and reused across both halves.
// grid (32 nt128, 32 b), block 256 (8 warps = 2 wm x 4 wn).
// mt==1 (k rows): epilogue stores exp(k-hat).
// ============================================================================
__global__ __launch_bounds__(256, 2)
void k_qkv_mma(const float* __restrict__ x) {
    extern __shared__ __half smh[];
    __half* a_s = smh;                         // 128*PITCH
    __half* xs  = smh + 128 * PITCH;           // 128*PITCH (128 tokens)
    float* red  = reinterpret_cast<float*>(smh + 256 * PITCH);  // 256
    float* invs = red + 256;                   // 128

    const int nt = blockIdx.x, b = blockIdx.y;
    const int tid = threadIdx.x;

    // ---- B: x tile [128 tok][128 ch] fp16, + ssq partials (once) ----
    {
        const int t = tid & 127, cq = tid >> 7;    // cq in {0,1}: 64 channels each
        const float* xc = x + (size_t)b * CCH * NTOK + (size_t)nt * 128 + t;
        float ss = 0.f;
        #pragma unroll
        for (int i = 0; i < 32; i++) {
            int c = cq * 64 + 2 * i;
            float v0 = xc[(size_t)c * NTOK];
            float v1 = xc[(size_t)(c + 1) * NTOK];
            ss += v0 * v0 + v1 * v1;
            *reinterpret_cast<__half2*>(&xs[t * PITCH + c]) = __floats2half2_rn(v0, v1);
        }
        red[cq * 128 + t] = ss;
    }
    __syncthreads();
    if (tid < 128)
        invs[tid] = 1.0f / fmaxf(sqrtf(red[tid] + red[128 + tid]), 1e-12f);
    __syncthreads();

    const int lane = tid & 31, w = tid >> 5;
    const int wm = w >> 2, wn = w & 3;
    const int r4 = lane >> 2, c4 = lane & 3;

    const uint32_t as_b = smem_u32(a_s);
    const uint32_t xs_b = smem_u32(xs);
    const uint32_t a_addr = as_b + ((wm * 64 + (lane & 15)) * PITCH + ((lane >> 4) << 3)) * 2;

    for (int mt = 0; mt < 3; mt++) {
        // ---- A: W tile [128 m][128 k] fp16 (coalesced) ----
        const uint32_t* wbh = reinterpret_cast<const uint32_t*>(g_wth) + mt * 8192;
        #pragma unroll
        for (int i = 0; i < 32; i++) {
            int idx = tid + i * 256;
            int m = idx >> 6, c2 = idx & 63;
            *reinterpret_cast<uint32_t*>(&a_s[m * PITCH + 2 * c2]) = wbh[idx];
        }
        __syncthreads();

        const bool is_k = (mt == 1);
        for (int half = 0; half < 2; half++) {
            const uint32_t b_addr = xs_b +
                ((half * 64 + wn * 16 + (lane & 7)) * PITCH + (((lane >> 3) & 1) << 3)) * 2;

            float acc[4][2][4];
            #pragma unroll
            for (int mi = 0; mi < 4; mi++)
                #pragma unroll
                for (int ni = 0; ni < 2; ni++)
                    #pragma unroll
                    for (int q = 0; q < 4; q++) acc[mi][ni][q] = 0.f;

            #pragma unroll
            for (int kc = 0; kc < 8; kc++) {
                uint32_t af[4][4], bf[2][2];
                #pragma unroll
                for (int mi = 0; mi < 4; mi++)
                    ldsm_x4(af[mi][0], af[mi][1], af[mi][2], af[mi][3],
                            a_addr + mi * (16 * PITCH * 2) + kc * 32);
                #pragma unroll
                for (int ni = 0; ni < 2; ni++)
                    ldsm_x2(bf[ni][0], bf[ni][1],
                            b_addr + ni * (8 * PITCH * 2) + kc * 32);
                #pragma unroll
                for (int mi = 0; mi < 4; mi++)
                    #pragma unroll
                    for (int ni = 0; ni < 2; ni++)
                        mma_f16(acc[mi][ni], af[mi][0], af[mi][1], af[mi][2], af[mi][3],
                                bf[ni][0], bf[ni][1]);
            }

            // ---- epilogue ----
            __half* outb = g_qkvh + ((size_t)b * QKV3 + (size_t)mt * 128) * NTOK
                           + (size_t)nt * 128 + half * 64;
            const float* invh = invs + half * 64;
            #pragma unroll
            for (int mi = 0; mi < 4; mi++) {
                #pragma unroll
                for (int ni = 0; ni < 2; ni++) {
                    int col = wn * 16 + ni * 8 + 2 * c4;
                    float i0 = invh[col], i1 = invh[col + 1];
                    int row0 = wm * 64 + mi * 16 + r4;
                    float v00 = acc[mi][ni][0] * i0, v01 = acc[mi][ni][1] * i1;
                    float v10 = acc[mi][ni][2] * i0, v11 = acc[mi][ni][3] * i1;
                    if (is_k) {
                        v00 = __expf(v00); v01 = __expf(v01);
                        v10 = __expf(v10); v11 = __expf(v11);
                    }
                    *reinterpret_cast<__half2*>(&outb[(size_t)row0 * NTOK + col]) =
                        __floats2half2_rn(v00, v01);
                    *reinterpret_cast<__half2*>(&outb[(size_t)(row0 + 8) * NTOK + col]) =
                        __floats2half2_rn(v10, v11);
                }
            }
        }
        __syncthreads();
    }
}

// ============================================================================
// K3: context partials on fp16 HMMA, 1024 tokens per block in 4 chunks of 256.
// grid 128*NSPLIT (=512), block 256.
// ============================================================================
__global__ __launch_bounds__(256)
void k_context() {
    __shared__ __half es[32 * 264];
    __shared__ __half vs[32 * 264];
    const int blk = blockIdx.x;
    const int bh = blk >> 2, split = blk & (NSPLIT - 1);
    const int b = bh >> 2, h = bh & 3;
    const int tid = threadIdx.x;

    const __half* kbase = g_qkvh + ((size_t)(b * QKV3 + CCH + h * DH)) * NTOK;
    const __half* vbase = g_qkvh + ((size_t)(b * QKV3 + 2 * CCH + h * DH)) * NTOK;

    const int w = tid >> 5, lane = tid & 31;
    const int mi = w >> 2, ni = w & 3;
    float dacc[4] = {0.f, 0.f, 0.f, 0.f};
    float zacc = 0.f;

    const uint32_t es_b = smem_u32(es);
    const uint32_t vs_b = smem_u32(vs);
    const uint32_t a_addr = es_b + ((mi * 16 + (lane & 15)) * 264 + ((lane >> 4) << 3)) * 2;
    const uint32_t b_addr = vs_b + ((ni * 8 + (lane & 7)) * 264 + (((lane >> 3) & 1) << 3)) * 2;
    const int zd = tid >> 3, zseg = (tid & 7) * 16;

    for (int chunk = 0; chunk < 4; chunk++) {
        const int t0 = split * 1024 + chunk * 256;

        #pragma unroll
        for (int j = 0; j < 16; j++) {
            int hidx = tid + j * 256;
            int d = hidx >> 7, col = hidx & 127;
            uint32_t kv = *reinterpret_cast<const uint32_t*>(
                &kbase[(size_t)d * NTOK + t0 + 2 * col]);
            uint32_t vv = *reinterpret_cast<const uint32_t*>(
                &vbase[(size_t)d * NTOK + t0 + 2 * col]);
            *reinterpret_cast<uint32_t*>(&es[d * 264 + 2 * col]) = kv;
            *reinterpret_cast<uint32_t*>(&vs[d * 264 + 2 * col]) = vv;
        }
        __syncthreads();

        #pragma unroll
        for (int j = 0; j < 16; j++) {
            __half2 hv = *reinterpret_cast<const __half2*>(&es[zd * 264 + 2 * (zseg + j)]);
            float2 f = __half22float2(hv);
            zacc += f.x + f.y;
        }

        #pragma unroll
        for (int kc = 0; kc < 16; kc++) {
            uint32_t a0, a1, a2, a3, b0, b1;
            ldsm_x4(a0, a1, a2, a3, a_addr + kc * 32);
            ldsm_x2(b0, b1, b_addr + kc * 32);
            mma_f16(dacc, a0, a1, a2, a3, b0, b1);
        }
        __syncthreads();
    }

    {
        float z = zacc;
        z += __shfl_xor_sync(0xFFFFFFFFu, z, 1);
        z += __shfl_xor_sync(0xFFFFFFFFu, z, 2);
        z += __shfl_xor_sync(0xFFFFFFFFu, z, 4);
        if ((tid & 7) == 0)
            g_zpart[split * (BATCH * NH * DH) + bh * 32 + zd] = z;
    }

    float* outp = g_ctx_part + ((size_t)split * 128 + bh) * 1024;
    const int r = lane >> 2, c2 = (lane & 3) * 2;
    const int dr = mi * 16 + r, ec = ni * 8 + c2;
    *reinterpret_cast<float2*>(&outp[dr * 32 + ec]) = make_float2(dacc[0], dacc[1]);
    *reinterpret_cast<float2*>(&outp[(dr + 8) * 32 + ec]) = make_float2(dacc[2], dacc[3]);
}

// ============================================================================
// K4: fold w_out through normalized context -> W2 fp16 [b][o][c].
// grid (32 b, 4 o-tiles, 4 heads), block 256.
// ============================================================================
__global__ void k_w2p(const float* __restrict__ wout, const float* __restrict__ mem_kv) {
    __shared__ float ce[32 * 36];
    __shared__ float ws[32 * 36];
    __shared__ float ews[128];
    __shared__ float invz[32];
    const int b = blockIdx.x, og = blockIdx.y, cg = blockIdx.z;
    const int tid = threadIdx.x;

    if (tid < 128)
        ews[tid] = __expf(mem_kv[cg * 128 + tid]);
    for (int idx = tid; idx < 1024; idx += 256) {
        int ol = idx >> 5, e = idx & 31;
        ws[ol * 36 + e] = wout[(og * 32 + ol) * 128 + cg * 32 + e];
    }
    __syncthreads();

    if (tid < 32) {
        float z = 0.f;
        #pragma unroll
        for (int s = 0; s < NSPLIT; s++)
            z += g_zpart[s * (BATCH * NH * DH) + b * 128 + cg * 32 + tid];
        z += ews[tid * 4] + ews[tid * 4 + 1] + ews[tid * 4 + 2] + ews[tid * 4 + 3];
        invz[tid] = 1.0f / z;
    }
    __syncthreads();

    {
        const int lc = tid >> 3, e4 = (tid & 7) * 4;
        const size_t base = (size_t)(b * 4 + cg) * 1024 + lc * 32 + e4;
        float4 v = make_float4(0.f, 0.f, 0.f, 0.f);
        #pragma unroll
        for (int s = 0; s < NSPLIT; s++) {
            float4 t = *reinterpret_cast<const float4*>(&g_ctx_part[(size_t)s * 131072 + base]);
            v.x += t.x; v.y += t.y; v.z += t.z; v.w += t.w;
        }
        #pragma unroll
        for (int j = 0; j < 4; j++) {
            float ew = ews[lc * 4 + j];
            v.x = fmaf(ew, mem_kv[512 + ((cg * 32 + e4 + 0) * 4 + j)], v.x);
            v.y = fmaf(ew, mem_kv[512 + ((cg * 32 + e4 + 1) * 4 + j)], v.y);
            v.z = fmaf(ew, mem_kv[512 + ((cg * 32 + e4 + 2) * 4 + j)], v.z);
            v.w = fmaf(ew, mem_kv[512 + ((cg * 32 + e4 + 3) * 4 + j)], v.w);
        }
        const float iz = invz[lc];
        v.x *= iz; v.y *= iz; v.z *= iz; v.w *= iz;
        *reinterpret_cast<float4*>(&ce[lc * 36 + e4]) = v;
    }
    __syncthreads();

    const int o_l = tid >> 3;
    const int cb = tid & 7;
    const float* wr = &ws[o_l * 36];
    #pragma unroll
    for (int ci = 0; ci < 4; ci++) {
        int c_l = cb + ci * 8;
        const float* cr = &ce[c_l * 36];
        float a = 0.f;
        #pragma unroll
        for (int e4 = 0; e4 < 32; e4 += 4) {
            float4 w4 = *reinterpret_cast<const float4*>(wr + e4);
            float4 c4v = *reinterpret_cast<const float4*>(cr + e4);
            a = fmaf(w4.x, c4v.x, a);
            a = fmaf(w4.y, c4v.y, a);
            a = fmaf(w4.z, c4v.z, a);
            a = fmaf(w4.w, c4v.w, a);
        }
        g_w2h[((size_t)b * 128 + og * 32 + o_l) * 128 + cg * 32 + c_l] = __float2half(a);
    }
}

// ============================================================================
// K5: fused q-softmax + output GEMM on fp16 HMMA + ldmatrix.
// CTA tile M=128(o) x N=64(t) x K=128(c).  grid (64 nt, 32 b), block 256.
// ============================================================================
__global__ __launch_bounds__(256, 2)
void k_final_mma(const float* __restrict__ bout, float* __restrict__ y) {
    extern __shared__ __half smh5[];
    __half* a_s = smh5;                        // 128*PITCH
    __half* xs  = smh5 + 128 * PITCH;          // 64*PITCH
    float* bs   = reinterpret_cast<float*>(smh5 + 192 * PITCH);  // 128

    const int nt = blockIdx.x, b = blockIdx.y;
    const int tid = threadIdx.x;

    const uint32_t* wgh = reinterpret_cast<const uint32_t*>(g_w2h) + (size_t)b * 8192;
    #pragma unroll
    for (int i = 0; i < 32; i++) {
        int idx = tid + i * 256;
        int o = idx >> 6, c2 = idx & 63;
        *reinterpret_cast<uint32_t*>(&a_s[o * PITCH + 2 * c2]) = wgh[idx];
    }

    {
        const int t = tid & 63, h = tid >> 6;
        const __half* qc = g_qkvh + (size_t)b * QKV3 * NTOK + (size_t)nt * 64 + t;
        float qv[32];
        float m = -1e30f;
        #pragma unroll
        for (int d = 0; d < 32; d++) {
            qv[d] = __half2float(qc[(size_t)(h * 32 + d) * NTOK]);
            m = fmaxf(m, qv[d]);
        }
        float ss = 0.f;
        #pragma unroll
        for (int d = 0; d < 32; d++) {
            qv[d] = __expf(qv[d] - m);
            ss += qv[d];
        }
        const float inv = 0.17677669529663687f / ss;
        #pragma unroll
        for (int d = 0; d < 32; d += 2) {
            *reinterpret_cast<__half2*>(&xs[t * PITCH + h * 32 + d]) =
                __floats2half2_rn(qv[d] * inv, qv[d + 1] * inv);
        }
    }
    if (tid < 128) bs[tid] = bout[tid];
    __syncthreads();

    const int lane = tid & 31, w = tid >> 5;
    const int wm = w >> 2, wn = w & 3;
    const int r4 = lane >> 2, c4 = lane & 3;

    const uint32_t as_b = smem_u32(a_s);
    const uint32_t xs_b = smem_u32(xs);
    const uint32_t a_addr = as_b + ((wm * 64 + (lane & 15)) * PITCH + ((lane >> 4) << 3)) * 2;
    const uint32_t b_addr = xs_b + ((wn * 16 + (lane & 7)) * PITCH + (((lane >> 3) & 1) << 3)) * 2;

    float acc[4][2][4];
    #pragma unroll
    for (int mi = 0; mi < 4; mi++)
        #pragma unroll
        for (int ni = 0; ni < 2; ni++)
            #pragma unroll
            for (int q = 0; q < 4; q++) acc[mi][ni][q] = 0.f;

    #pragma unroll
    for (int kc = 0; kc < 8; kc++) {
        uint32_t af[4][4], bf[2][2];
        #pragma unroll
        for (int mi = 0; mi < 4; mi++)
            ldsm_x4(af[mi][0], af[mi][1], af[mi][2], af[mi][3],
                    a_addr + mi * (16 * PITCH * 2) + kc * 32);
        #pragma unroll
        for (int ni = 0; ni < 2; ni++)
            ldsm_x2(bf[ni][0], bf[ni][1],
                    b_addr + ni * (8 * PITCH * 2) + kc * 32);
        #pragma unroll
        for (int mi = 0; mi < 4; mi++)
            #pragma unroll
            for (int ni = 0; ni < 2; ni++)
                mma_f16(acc[mi][ni], af[mi][0], af[mi][1], af[mi][2], af[mi][3],
                        bf[ni][0], bf[ni][1]);
    }

    float* outb = y + (size_t)b * CCH * NTOK + (size_t)nt * 64;
    #pragma unroll
    for (int mi = 0; mi < 4; mi++) {
        #pragma unroll
        for (int ni = 0; ni < 2; ni++) {
            int col = wn * 16 + ni * 8 + 2 * c4;
            int row0 = wm * 64 + mi * 16 + r4;
            float b0 = bs[row0], b1 = bs[row0 + 8];
            float2 v0 = make_float2(acc[mi][ni][0] + b0, acc[mi][ni][1] + b0);
            float2 v1 = make_float2(acc[mi][ni][2] + b1, acc[mi][ni][3] + b1);
            *reinterpret_cast<float2*>(&outb[(size_t)row0 * NTOK + col]) = v0;
            *reinterpret_cast<float2*>(&outb[(size_t)(row0 + 8) * NTOK + col]) = v1;
        }
    }
}

// ============================================================================
extern "C" void kernel_launch(void* const* d_in, const int* in_sizes, int n_in,
                              void* d_out, int out_size) {
    const float* x      = (const float*)d_in[0];
    const float* g      = (const float*)d_in[1];
    const float* wqkv   = (const float*)d_in[2];
    const float* mem_kv = (const float*)d_in[3];
    const float* wout   = (const float*)d_in[4];
    const float* bout   = (const float*)d_in[5];
    float* y = (float*)d_out;

    const int SMEM_K1 = 256 * PITCH * 2 + 384 * 4;   // 71168 B
    const int SMEM_K5 = 192 * PITCH * 2 + 128 * 4;   // 52736 B
    cudaFuncSetAttribute(k_qkv_mma,   cudaFuncAttributeMaxDynamicSharedMemorySize, SMEM_K1);
    cudaFuncSetAttribute(k_final_mma, cudaFuncAttributeMaxDynamicSharedMemorySize, SMEM_K5);

    k_prepw<<<192, 256>>>(wqkv, g);
    k_qkv_mma<<<dim3(32, 32), 256, SMEM_K1>>>(x);
    k_context<<<128 * NSPLIT, 256>>>();
    k_w2p<<<dim3(32, 4, 4), 256>>>(wout, mem_kv);
    k_final_mma<<<dim3(64, 32), 256, SMEM_K5>>>(bout, y);
}